// round 9
// baseline (speedup 1.0000x reference)
#include <cuda_runtime.h>
#include <cstdint>

// Problem constants
#define N_INN   50000
#define NC      64
#define NT      8
#define NE      800000
#define N_OUTN  50000
#define NF      64
#define KD      512   // NT*NC

// GEMM tiling
#define BM      128
#define NITER   (KD / 32)                 // 16
#define AS_STRIDE 36                      // words; 144B = 9*16 (16B-aligned rows)
#define BS_STRIDE 72                      // words; 288B = 18*16
#define AS_WORDS  (BM * AS_STRIDE)        // 4608 per stage
#define BS_WORDS  (32 * BS_STRIDE)        // 2304 per stage
#define GEMM_SMEM_WORDS (2 * AS_WORDS + 2 * BS_WORDS)   // 13824
#define GEMM_SMEM_BYTES (GEMM_SMEM_WORDS * 4)           // 55296

// ---------------- scratch (static device allocations only; zero-initialized) ----------------
static __device__ int      g_count[N_OUTN];     // zero at load; re-zeroed by k_scan1 each run
static __device__ int      g_offset[N_OUTN + 1];
static __device__ int      g_cursor[N_OUTN];
static __device__ int      g_in_sorted[NE];
static __device__ float4   g_ef_sorted[NE * 2];            // 8 floats / edge, sorted
static __device__ uint32_t g_agg[(size_t)N_OUTN * KD];     // tf32 bits, 102.4 MB
static __device__ uint32_t g_ktf[KD * NF];                 // Kmat as tf32 bits

__device__ __forceinline__ int clampi(int v, int hi) {
    v = v < 0 ? 0 : v;
    return v >= hi ? hi - 1 : v;
}

__device__ __forceinline__ uint32_t f2tf32(float f) {
    uint32_t u;
    asm("cvt.rna.tf32.f32 %0, %1;" : "=r"(u) : "f"(f));
    return u;
}

__device__ __forceinline__ void cp16(uint32_t dst_smem, const void* src, bool valid) {
    int sz = valid ? 16 : 0;
    asm volatile("cp.async.cg.shared.global [%0], [%1], 16, %2;\n"
                 :: "r"(dst_smem), "l"(src), "r"(sz));
}

// ---------------- k1: histogram + Kmat tf32 conversion ----------------
__global__ void k_hist(const int* __restrict__ idx, const float* __restrict__ Kmat) {
    int e = blockIdx.x * blockDim.x + threadIdx.x;
    if (e < KD * NF) g_ktf[e] = f2tf32(Kmat[e]);
    if (e < NE) {
        int o = clampi(idx[2 * e], N_OUTN);
        atomicAdd(&g_count[o], 1);
    }
}

// ---------------- k2: single-block tiled exclusive scan (also re-zeros g_count) ----------------
__global__ __launch_bounds__(1024) void k_scan1() {
    __shared__ int wsum[32];
    __shared__ int s_tot;
    int tid = threadIdx.x, lane = tid & 31, wid = tid >> 5;
    int running = 0;

    const int NTILE = (N_OUTN + 1023) / 1024;   // 49
    for (int tile = 0; tile < NTILE; tile++) {
        int i = tile * 1024 + tid;
        int v = (i < N_OUTN) ? g_count[i] : 0;
        int x = v;
#pragma unroll
        for (int off = 1; off < 32; off <<= 1) {
            int y = __shfl_up_sync(0xffffffffu, x, off);
            if (lane >= off) x += y;
        }
        if (lane == 31) wsum[wid] = x;
        __syncthreads();
        if (wid == 0) {
            int w = wsum[lane];
            int y = w;
#pragma unroll
            for (int off = 1; off < 32; off <<= 1) {
                int z = __shfl_up_sync(0xffffffffu, y, off);
                if (lane >= off) y += z;
            }
            wsum[lane] = y - w;          // exclusive warp prefix
            if (lane == 31) s_tot = y;   // tile total
        }
        __syncthreads();
        int excl = running + (x - v) + wsum[wid];
        if (i < N_OUTN) {
            g_offset[i] = excl;
            g_cursor[i] = excl;
            g_count[i]  = 0;             // restore invariant for next run
        }
        running += s_tot;
        __syncthreads();                 // protect wsum/s_tot before next tile
    }
    if (tid == 0) g_offset[N_OUTN] = NE;
}

// ---------------- k3: permute edges into segment-sorted order ----------------
__global__ void k_permute(const int* __restrict__ idx,
                          const float* __restrict__ ef) {
    int e = blockIdx.x * blockDim.x + threadIdx.x;
    if (e >= NE) return;
    int o  = clampi(idx[2 * e],     N_OUTN);
    int in = clampi(idx[2 * e + 1], N_INN);
    int pos = atomicAdd(&g_cursor[o], 1);
    pos = clampi(pos, NE);
    g_in_sorted[pos] = in;
    float4 v0, v1;
    v0.x = ef[0 * NE + e]; v0.y = ef[1 * NE + e];
    v0.z = ef[2 * NE + e]; v0.w = ef[3 * NE + e];
    v1.x = ef[4 * NE + e]; v1.y = ef[5 * NE + e];
    v1.z = ef[6 * NE + e]; v1.w = ef[7 * NE + e];
    g_ef_sorted[pos * 2]     = v0;
    g_ef_sorted[pos * 2 + 1] = v1;
}

// ---------------- k4: per-output-node aggregation (one warp / node, unroll-4) ----------------
__device__ __forceinline__ void fma16(float acc[16], float4 e0, float4 e1,
                                      float a0, float a1) {
    acc[0]  += e0.x * a0;  acc[1]  += e0.x * a1;
    acc[2]  += e0.y * a0;  acc[3]  += e0.y * a1;
    acc[4]  += e0.z * a0;  acc[5]  += e0.z * a1;
    acc[6]  += e0.w * a0;  acc[7]  += e0.w * a1;
    acc[8]  += e1.x * a0;  acc[9]  += e1.x * a1;
    acc[10] += e1.y * a0;  acc[11] += e1.y * a1;
    acc[12] += e1.z * a0;  acc[13] += e1.z * a1;
    acc[14] += e1.w * a0;  acc[15] += e1.w * a1;
}

__global__ __launch_bounds__(256) void k_agg(const float* __restrict__ nf) {
    int gw   = (blockIdx.x * blockDim.x + threadIdx.x) >> 5;
    int lane = threadIdx.x & 31;
    if (gw >= N_OUTN) return;
    int start = g_offset[gw];
    int end   = g_offset[gw + 1];

    float acc[16];
#pragma unroll
    for (int i = 0; i < 16; i++) acc[i] = 0.f;

    int p = start;
    for (; p + 4 <= end; p += 4) {
        int in0 = g_in_sorted[p];
        int in1 = g_in_sorted[p + 1];
        int in2 = g_in_sorted[p + 2];
        int in3 = g_in_sorted[p + 3];
        float4 e00 = g_ef_sorted[p * 2 + 0], e01 = g_ef_sorted[p * 2 + 1];
        float4 e10 = g_ef_sorted[p * 2 + 2], e11 = g_ef_sorted[p * 2 + 3];
        float4 e20 = g_ef_sorted[p * 2 + 4], e21 = g_ef_sorted[p * 2 + 5];
        float4 e30 = g_ef_sorted[p * 2 + 6], e31 = g_ef_sorted[p * 2 + 7];
        float a00 = nf[in0 * NC + lane],      a01 = nf[in0 * NC + 32 + lane];
        float a10 = nf[in1 * NC + lane],      a11 = nf[in1 * NC + 32 + lane];
        float a20 = nf[in2 * NC + lane],      a21 = nf[in2 * NC + 32 + lane];
        float a30 = nf[in3 * NC + lane],      a31 = nf[in3 * NC + 32 + lane];
        fma16(acc, e00, e01, a00, a01);
        fma16(acc, e10, e11, a10, a11);
        fma16(acc, e20, e21, a20, a21);
        fma16(acc, e30, e31, a30, a31);
    }
    for (; p < end; p++) {
        int in0 = g_in_sorted[p];
        float4 e00 = g_ef_sorted[p * 2], e01 = g_ef_sorted[p * 2 + 1];
        float a00 = nf[in0 * NC + lane], a01 = nf[in0 * NC + 32 + lane];
        fma16(acc, e00, e01, a00, a01);
    }

    uint32_t* dst = g_agg + (size_t)gw * KD;
#pragma unroll
    for (int t = 0; t < NT; t++) {
        dst[t * 64 + lane]      = f2tf32(acc[2 * t]);
        dst[t * 64 + 32 + lane] = f2tf32(acc[2 * t + 1]);
    }
}

// ---------------- k5: TF32 GEMM, cp.async double-buffered ----------------
// out(50000x64) = Agg(50000x512) @ Ktf(512x64) + bias
// 256 threads (8 warps), BM=128, BK=32. Warp w: rows m0+16w..16w+15, full n=64.
extern __shared__ uint32_t sgm[];

__global__ __launch_bounds__(256) void k_gemm(const float* __restrict__ bias,
                                              float* __restrict__ out) {
    int tid  = threadIdx.x;
    int warp = tid >> 5;
    int lane = tid & 31;
    int gid  = lane >> 2;     // 0..7
    int tig  = lane & 3;      // 0..3
    int m0   = blockIdx.x * BM;

    uint32_t sbase = (uint32_t)__cvta_generic_to_shared(sgm);

    // Staging indices (computed once)
    // A: 1024 chunks of 16B; 4 per thread. chunk q: row=q>>3 (0..127), c4=q&7
    // B: 512 chunks; 2 per thread. chunk q: kk=q>>4 (0..31), n4=q&15
    float acc[8][4];
#pragma unroll
    for (int nt = 0; nt < 8; nt++)
#pragma unroll
        for (int j = 0; j < 4; j++) acc[nt][j] = 0.f;

    // ---- stage 0 prologue ----
    {
        const int k0 = 0, s = 0;
#pragma unroll
        for (int i = 0; i < 4; i++) {
            int q = tid + i * 256, row = q >> 3, c4 = q & 7;
            int gm = m0 + row;
            bool v = gm < N_OUTN;
            const uint32_t* src = g_agg + (size_t)(v ? gm : N_OUTN - 1) * KD + k0 + c4 * 4;
            cp16(sbase + (s * AS_WORDS + row * AS_STRIDE + c4 * 4) * 4, src, v);
        }
#pragma unroll
        for (int i = 0; i < 2; i++) {
            int q = tid + i * 256, kk = q >> 4, n4 = q & 15;
            cp16(sbase + (2 * AS_WORDS + s * BS_WORDS + kk * BS_STRIDE + n4 * 4) * 4,
                 g_ktf + (k0 + kk) * 64 + n4 * 4, true);
        }
        asm volatile("cp.async.commit_group;\n");
    }

    for (int it = 0; it < NITER; it++) {
        if (it + 1 < NITER) {
            const int k0 = (it + 1) * 32, s = (it + 1) & 1;
#pragma unroll
            for (int i = 0; i < 4; i++) {
                int q = tid + i * 256, row = q >> 3, c4 = q & 7;
                int gm = m0 + row;
                bool v = gm < N_OUTN;
                const uint32_t* src = g_agg + (size_t)(v ? gm : N_OUTN - 1) * KD + k0 + c4 * 4;
                cp16(sbase + (s * AS_WORDS + row * AS_STRIDE + c4 * 4) * 4, src, v);
            }
#pragma unroll
            for (int i = 0; i < 2; i++) {
                int q = tid + i * 256, kk = q >> 4, n4 = q & 15;
                cp16(sbase + (2 * AS_WORDS + s * BS_WORDS + kk * BS_STRIDE + n4 * 4) * 4,
                     g_ktf + (k0 + kk) * 64 + n4 * 4, true);
            }
            asm volatile("cp.async.commit_group;\n");
            asm volatile("cp.async.wait_group 1;\n");
        } else {
            asm volatile("cp.async.wait_group 0;\n");
        }
        __syncthreads();

        const uint32_t* As = sgm + (it & 1) * AS_WORDS;
        const uint32_t* Bs = sgm + 2 * AS_WORDS + (it & 1) * BS_WORDS;
        int wm = warp * 16;
#pragma unroll
        for (int kk = 0; kk < 32; kk += 8) {
            uint32_t a0 = As[(wm + gid) * AS_STRIDE + kk + tig];
            uint32_t a1 = As[(wm + gid + 8) * AS_STRIDE + kk + tig];
            uint32_t a2 = As[(wm + gid) * AS_STRIDE + kk + tig + 4];
            uint32_t a3 = As[(wm + gid + 8) * AS_STRIDE + kk + tig + 4];
#pragma unroll
            for (int nt = 0; nt < 8; nt++) {
                uint32_t b0 = Bs[(kk + tig) * BS_STRIDE + nt * 8 + gid];
                uint32_t b1 = Bs[(kk + tig + 4) * BS_STRIDE + nt * 8 + gid];
                asm volatile(
                    "mma.sync.aligned.m16n8k8.row.col.f32.tf32.tf32.f32 "
                    "{%0,%1,%2,%3}, {%4,%5,%6,%7}, {%8,%9}, {%0,%1,%2,%3};\n"
                    : "+f"(acc[nt][0]), "+f"(acc[nt][1]),
                      "+f"(acc[nt][2]), "+f"(acc[nt][3])
                    : "r"(a0), "r"(a1), "r"(a2), "r"(a3), "r"(b0), "r"(b1));
            }
        }
        __syncthreads();
    }

    // Epilogue
    int mA = m0 + warp * 16 + gid;
    int mB = mA + 8;
#pragma unroll
    for (int nt = 0; nt < 8; nt++) {
        int n = nt * 8 + tig * 2;
        float b0 = bias[n], b1 = bias[n + 1];
        if (mA < N_OUTN) {
            float2 v; v.x = acc[nt][0] + b0; v.y = acc[nt][1] + b1;
            *(float2*)(out + (size_t)mA * NF + n) = v;
        }
        if (mB < N_OUTN) {
            float2 v; v.x = acc[nt][2] + b0; v.y = acc[nt][3] + b1;
            *(float2*)(out + (size_t)mB * NF + n) = v;
        }
    }
}

// ---------------- launch ----------------
extern "C" void kernel_launch(void* const* d_in, const int* in_sizes, int n_in,
                              void* d_out, int out_size) {
    const float* nf   = (const float*)d_in[0];   // node_features (50000,64)
    const float* ef   = (const float*)d_in[1];   // edge_features (8,800000)
    const int*   idx  = (const int*)d_in[2];     // indices (800000,2) int32
    const float* Kmat = (const float*)d_in[3];   // kernel (8,64,64)
    const float* bias = (const float*)d_in[4];   // bias (64,)
    float*       out  = (float*)d_out;           // (50000,64)

    cudaFuncSetAttribute(k_gemm, cudaFuncAttributeMaxDynamicSharedMemorySize,
                         GEMM_SMEM_BYTES);

    k_hist   <<<(NE + 255) / 256, 256>>>(idx, Kmat);
    k_scan1  <<<1, 1024>>>();
    k_permute<<<(NE + 255) / 256, 256>>>(idx, ef);
    k_agg    <<<(N_OUTN * 32 + 255) / 256, 256>>>(nf);   // launch #4 -> profiled
    k_gemm   <<<(N_OUTN + BM - 1) / BM, 256, GEMM_SMEM_BYTES>>>(bias, out);
}

// round 12
// speedup vs baseline: 1.0971x; 1.0971x over previous
#include <cuda_runtime.h>
#include <cstdint>

// Problem constants
#define N_INN   50000
#define NC      64
#define NT      8
#define NE      800000
#define N_OUTN  50000
#define NF      64
#define KD      512   // NT*NC
#define NBLK_SCAN 196 // ceil(50000/256)

// GEMM tiling
#define BM      128
#define NITER   (KD / 32)                 // 16
#define AS_STRIDE 36
#define BS_STRIDE 72
#define AS_WORDS  (BM * AS_STRIDE)
#define BS_WORDS  (32 * BS_STRIDE)
#define GEMM_SMEM_WORDS (2 * AS_WORDS + 2 * BS_WORDS)
#define GEMM_SMEM_BYTES (GEMM_SMEM_WORDS * 4)   // 55296

// ---------------- scratch (static device allocations; zero-initialized at load) ----------------
static __device__ int      g_count[N_OUTN];     // re-zeroed by k_scan_a each run
static __device__ int      g_offset[N_OUTN + 1];
static __device__ int      g_cursor[N_OUTN];
static __device__ int      g_bsum[NBLK_SCAN];
static __device__ int      g_in_sorted[NE];
static __device__ float4   g_ef_sorted[NE * 2];            // 8 floats / edge, sorted
static __device__ uint32_t g_agg[(size_t)N_OUTN * KD];     // tf32 bits, 102.4 MB
static __device__ uint32_t g_ktf[KD * NF];                 // Kmat as tf32 bits

__device__ __forceinline__ int clampi(int v, int hi) {
    v = v < 0 ? 0 : v;
    return v >= hi ? hi - 1 : v;
}

__device__ __forceinline__ uint32_t f2tf32(float f) {
    uint32_t u;
    asm("cvt.rna.tf32.f32 %0, %1;" : "=r"(u) : "f"(f));
    return u;
}

__device__ __forceinline__ void cp16(uint32_t dst_smem, const void* src, bool valid) {
    int sz = valid ? 16 : 0;
    asm volatile("cp.async.cg.shared.global [%0], [%1], 16, %2;\n"
                 :: "r"(dst_smem), "l"(src), "r"(sz));
}

// ---------------- k1: histogram + Kmat tf32 conversion ----------------
__global__ void k_hist(const int* __restrict__ idx, const float* __restrict__ Kmat) {
    int e = blockIdx.x * blockDim.x + threadIdx.x;
    if (e < KD * NF) g_ktf[e] = f2tf32(Kmat[e]);
    if (e < NE) {
        int o = clampi(idx[2 * e], N_OUTN);
        atomicAdd(&g_count[o], 1);
    }
}

// ---------------- parallel coalesced exclusive scan (3 kernels) ----------------
__device__ __forceinline__ int block_scan_excl(int v, int* wsum, int* block_total) {
    int tid = threadIdx.x, lane = tid & 31, wid = tid >> 5;
    int x = v;
#pragma unroll
    for (int off = 1; off < 32; off <<= 1) {
        int y = __shfl_up_sync(0xffffffffu, x, off);
        if (lane >= off) x += y;
    }
    if (lane == 31) wsum[wid] = x;
    __syncthreads();
    if (tid == 0) {
        int run = 0;
#pragma unroll
        for (int j = 0; j < 8; j++) { int t = wsum[j]; wsum[j] = run; run += t; }
        *block_total = run;
    }
    __syncthreads();
    return x - v + wsum[wid];
}

__global__ void k_scan_a() {
    __shared__ int wsum[8];
    __shared__ int btot;
    int i = blockIdx.x * 256 + threadIdx.x;
    int v = 0;
    if (i < N_OUTN) {
        v = g_count[i];
        g_count[i] = 0;              // restore invariant for next run
    }
    int excl = block_scan_excl(v, wsum, &btot);
    if (i < N_OUTN) g_offset[i] = excl;
    if (threadIdx.x == 0) g_bsum[blockIdx.x] = btot;
}

__global__ void k_scan_b() {
    __shared__ int wsum[8];
    __shared__ int btot;
    int tid = threadIdx.x;
    int v = (tid < NBLK_SCAN) ? g_bsum[tid] : 0;
    int excl = block_scan_excl(v, wsum, &btot);
    if (tid < NBLK_SCAN) g_bsum[tid] = excl;
}

__global__ void k_scan_c() {
    int i = blockIdx.x * 256 + threadIdx.x;
    if (i < N_OUTN) {
        int v = g_offset[i] + g_bsum[blockIdx.x];
        g_offset[i] = v;
        g_cursor[i] = v;
    }
    if (i == 0) g_offset[N_OUTN] = NE;
}

// ---------------- k4: permute edges into segment-sorted order ----------------
__global__ void k_permute(const int* __restrict__ idx,
                          const float* __restrict__ ef) {
    int e = blockIdx.x * blockDim.x + threadIdx.x;
    if (e >= NE) return;
    int o  = clampi(idx[2 * e],     N_OUTN);
    int in = clampi(idx[2 * e + 1], N_INN);
    int pos = atomicAdd(&g_cursor[o], 1);
    pos = clampi(pos, NE);
    g_in_sorted[pos] = in;
    float4 v0, v1;
    v0.x = ef[0 * NE + e]; v0.y = ef[1 * NE + e];
    v0.z = ef[2 * NE + e]; v0.w = ef[3 * NE + e];
    v1.x = ef[4 * NE + e]; v1.y = ef[5 * NE + e];
    v1.z = ef[6 * NE + e]; v1.w = ef[7 * NE + e];
    g_ef_sorted[pos * 2]     = v0;
    g_ef_sorted[pos * 2 + 1] = v1;
}

// ---------------- k5: aggregation — TWO warps per node (c-halves) ----------------
__device__ __forceinline__ void fma8(float acc[8], float4 e0, float4 e1, float a) {
    acc[0] += e0.x * a;  acc[1] += e0.y * a;
    acc[2] += e0.z * a;  acc[3] += e0.w * a;
    acc[4] += e1.x * a;  acc[5] += e1.y * a;
    acc[6] += e1.z * a;  acc[7] += e1.w * a;
}

__global__ __launch_bounds__(256) void k_agg(const float* __restrict__ nf) {
    int gw2  = (blockIdx.x * blockDim.x + threadIdx.x) >> 5;  // global warp id
    int lane = threadIdx.x & 31;
    int node = gw2 >> 1;
    int half = gw2 & 1;
    if (node >= N_OUTN) return;
    int start = g_offset[node];
    int end   = g_offset[node + 1];
    int coff  = half * 32 + lane;        // this warp's c column

    float acc[8];
#pragma unroll
    for (int i = 0; i < 8; i++) acc[i] = 0.f;

    int p = start;
    for (; p + 2 <= end; p += 2) {
        int in0 = g_in_sorted[p];
        int in1 = g_in_sorted[p + 1];
        float4 e00 = g_ef_sorted[p * 2 + 0], e01 = g_ef_sorted[p * 2 + 1];
        float4 e10 = g_ef_sorted[p * 2 + 2], e11 = g_ef_sorted[p * 2 + 3];
        float a0 = nf[in0 * NC + coff];
        float a1 = nf[in1 * NC + coff];
        fma8(acc, e00, e01, a0);
        fma8(acc, e10, e11, a1);
    }
    if (p < end) {
        int in0 = g_in_sorted[p];
        float4 e00 = g_ef_sorted[p * 2], e01 = g_ef_sorted[p * 2 + 1];
        float a0 = nf[in0 * NC + coff];
        fma8(acc, e00, e01, a0);
    }

    uint32_t* dst = g_agg + (size_t)node * KD;
#pragma unroll
    for (int t = 0; t < NT; t++)
        dst[t * 64 + coff] = f2tf32(acc[t]);
}

// ---------------- k6: TF32 GEMM, cp.async double-buffered (validated R9) ----------------
extern __shared__ uint32_t sgm[];

__global__ __launch_bounds__(256) void k_gemm(const float* __restrict__ bias,
                                              float* __restrict__ out) {
    int tid  = threadIdx.x;
    int warp = tid >> 5;
    int lane = tid & 31;
    int gid  = lane >> 2;
    int tig  = lane & 3;
    int m0   = blockIdx.x * BM;

    uint32_t sbase = (uint32_t)__cvta_generic_to_shared(sgm);

    float acc[8][4];
#pragma unroll
    for (int nt = 0; nt < 8; nt++)
#pragma unroll
        for (int j = 0; j < 4; j++) acc[nt][j] = 0.f;

    {
        const int k0 = 0, s = 0;
#pragma unroll
        for (int i = 0; i < 4; i++) {
            int q = tid + i * 256, row = q >> 3, c4 = q & 7;
            int gm = m0 + row;
            bool v = gm < N_OUTN;
            const uint32_t* src = g_agg + (size_t)(v ? gm : N_OUTN - 1) * KD + k0 + c4 * 4;
            cp16(sbase + (s * AS_WORDS + row * AS_STRIDE + c4 * 4) * 4, src, v);
        }
#pragma unroll
        for (int i = 0; i < 2; i++) {
            int q = tid + i * 256, kk = q >> 4, n4 = q & 15;
            cp16(sbase + (2 * AS_WORDS + s * BS_WORDS + kk * BS_STRIDE + n4 * 4) * 4,
                 g_ktf + (k0 + kk) * 64 + n4 * 4, true);
        }
        asm volatile("cp.async.commit_group;\n");
    }

    for (int it = 0; it < NITER; it++) {
        if (it + 1 < NITER) {
            const int k0 = (it + 1) * 32, s = (it + 1) & 1;
#pragma unroll
            for (int i = 0; i < 4; i++) {
                int q = tid + i * 256, row = q >> 3, c4 = q & 7;
                int gm = m0 + row;
                bool v = gm < N_OUTN;
                const uint32_t* src = g_agg + (size_t)(v ? gm : N_OUTN - 1) * KD + k0 + c4 * 4;
                cp16(sbase + (s * AS_WORDS + row * AS_STRIDE + c4 * 4) * 4, src, v);
            }
#pragma unroll
            for (int i = 0; i < 2; i++) {
                int q = tid + i * 256, kk = q >> 4, n4 = q & 15;
                cp16(sbase + (2 * AS_WORDS + s * BS_WORDS + kk * BS_STRIDE + n4 * 4) * 4,
                     g_ktf + (k0 + kk) * 64 + n4 * 4, true);
            }
            asm volatile("cp.async.commit_group;\n");
            asm volatile("cp.async.wait_group 1;\n");
        } else {
            asm volatile("cp.async.wait_group 0;\n");
        }
        __syncthreads();

        const uint32_t* As = sgm + (it & 1) * AS_WORDS;
        const uint32_t* Bs = sgm + 2 * AS_WORDS + (it & 1) * BS_WORDS;
        int wm = warp * 16;
#pragma unroll
        for (int kk = 0; kk < 32; kk += 8) {
            uint32_t a0 = As[(wm + gid) * AS_STRIDE + kk + tig];
            uint32_t a1 = As[(wm + gid + 8) * AS_STRIDE + kk + tig];
            uint32_t a2 = As[(wm + gid) * AS_STRIDE + kk + tig + 4];
            uint32_t a3 = As[(wm + gid + 8) * AS_STRIDE + kk + tig + 4];
#pragma unroll
            for (int nt = 0; nt < 8; nt++) {
                uint32_t b0 = Bs[(kk + tig) * BS_STRIDE + nt * 8 + gid];
                uint32_t b1 = Bs[(kk + tig + 4) * BS_STRIDE + nt * 8 + gid];
                asm volatile(
                    "mma.sync.aligned.m16n8k8.row.col.f32.tf32.tf32.f32 "
                    "{%0,%1,%2,%3}, {%4,%5,%6,%7}, {%8,%9}, {%0,%1,%2,%3};\n"
                    : "+f"(acc[nt][0]), "+f"(acc[nt][1]),
                      "+f"(acc[nt][2]), "+f"(acc[nt][3])
                    : "r"(a0), "r"(a1), "r"(a2), "r"(a3), "r"(b0), "r"(b1));
            }
        }
        __syncthreads();
    }

    int mA = m0 + warp * 16 + gid;
    int mB = mA + 8;
#pragma unroll
    for (int nt = 0; nt < 8; nt++) {
        int n = nt * 8 + tig * 2;
        float b0 = bias[n], b1 = bias[n + 1];
        if (mA < N_OUTN) {
            float2 v; v.x = acc[nt][0] + b0; v.y = acc[nt][1] + b1;
            *(float2*)(out + (size_t)mA * NF + n) = v;
        }
        if (mB < N_OUTN) {
            float2 v; v.x = acc[nt][2] + b0; v.y = acc[nt][3] + b1;
            *(float2*)(out + (size_t)mB * NF + n) = v;
        }
    }
}

// ---------------- launch ----------------
extern "C" void kernel_launch(void* const* d_in, const int* in_sizes, int n_in,
                              void* d_out, int out_size) {
    const float* nf   = (const float*)d_in[0];   // node_features (50000,64)
    const float* ef   = (const float*)d_in[1];   // edge_features (8,800000)
    const int*   idx  = (const int*)d_in[2];     // indices (800000,2) int32
    const float* Kmat = (const float*)d_in[3];   // kernel (8,64,64)
    const float* bias = (const float*)d_in[4];   // bias (64,)
    float*       out  = (float*)d_out;           // (50000,64)

    cudaFuncSetAttribute(k_gemm, cudaFuncAttributeMaxDynamicSharedMemorySize,
                         GEMM_SMEM_BYTES);

    k_hist   <<<(NE + 255) / 256, 256>>>(idx, Kmat);
    k_scan_a <<<NBLK_SCAN, 256>>>();
    k_scan_b <<<1, 256>>>();
    k_scan_c <<<NBLK_SCAN, 256>>>();
    k_permute<<<(NE + 255) / 256, 256>>>(idx, ef);
    k_agg    <<<(N_OUTN * 2 * 32 + 255) / 256, 256>>>(nf);
    k_gemm   <<<(N_OUTN + BM - 1) / BM, 256, GEMM_SMEM_BYTES>>>(bias, out);
}